// round 11
// baseline (speedup 1.0000x reference)
#include <cuda_runtime.h>

// ---------------------------------------------------------------------------
// Compile-time Clebsch-Gordan coefficients (Racah formula), matching numpy ref.
// ---------------------------------------------------------------------------

__host__ __device__ constexpr double cfact(int n) {
    double r = 1.0;
    for (int i = 2; i <= n; ++i) r *= (double)i;
    return r;
}

__host__ __device__ constexpr double csqrt_(double x) {
    if (x <= 0.0) return 0.0;
    double g = x > 1.0 ? x : 1.0;
    for (int i = 0; i < 100; ++i) g = 0.5 * (g + x / g);
    return g;
}

__host__ __device__ constexpr double cg_elem(int l1, int l2, int L, int m1, int m2) {
    const int M = m1 + m2;
    if (M < -L || M > L) return 0.0;
    const double pref0 = csqrt_((2.0 * L + 1.0) * cfact(L + l1 - l2) * cfact(L - l1 + l2) *
                                cfact(l1 + l2 - L) / cfact(l1 + l2 + L + 1));
    const double pref = pref0 * csqrt_(cfact(L + M) * cfact(L - M) * cfact(l1 - m1) *
                                       cfact(l1 + m1) * cfact(l2 - m2) * cfact(l2 + m2));
    double s = 0.0;
    for (int k = 0; k <= l1 + l2 - L; ++k) {
        if (l1 - m1 - k < 0 || l2 + m2 - k < 0 || L - l2 + m1 + k < 0 || L - l1 - m2 + k < 0)
            continue;
        const double d = cfact(k) * cfact(l1 + l2 - L - k) * cfact(l1 - m1 - k) *
                         cfact(l2 + m2 - k) * cfact(L - l2 + m1 + k) * cfact(L - l1 - m2 + k);
        s += ((k & 1) ? -1.0 : 1.0) / d;
    }
    return pref * s;
}

__host__ __device__ constexpr bool cg_nz(double c) { return c > 1e-12 || c < -1e-12; }

__host__ __device__ constexpr bool okL(int l1, int l2, int L, int a, int b) {
    const int off = l1 + l2 - L;
    const int mu = a + b - off;
    return mu >= 0 && mu <= 2 * L && cg_nz(cg_elem(l1, l2, L, a - l1, b - l2));
}

__host__ __device__ constexpr bool pair_any(int l1, int l2, int Lmin, int Lmax,
                                            int p, int q, int m, int n) {
    for (int L = Lmin; L <= Lmax; ++L)
        if (okL(l1, l2, L, m, n) && okL(l1, l2, L, p, q)) return true;
    return false;
}

__host__ __device__ constexpr bool col_any_p(int l1, int l2, int Lmin, int Lmax, int p, int q) {
    for (int L = Lmin; L <= Lmax; ++L)
        if (okL(l1, l2, L, p, q)) return true;
    return false;
}

// exists a parity-owned valid p for this q?
__host__ __device__ constexpr bool col_any_q_par(int l1, int l2, int Lmin, int Lmax,
                                                 int q, bool sym, int PAR) {
    const int pmax = sym ? q : 2 * l1;
    for (int p = 0; p <= pmax; ++p)
        if (((p + q) & 1) == PAR && col_any_p(l1, l2, Lmin, Lmax, p, q)) return true;
    return false;
}

__host__ __device__ constexpr bool row_any(int l1, int l2, int Lmin, int Lmax,
                                           int p, int q, int m, int nlo) {
    for (int nn = nlo; nn <= 2 * l2; ++nn)
        if (pair_any(l1, l2, Lmin, Lmax, p, q, m, nn)) return true;
    return false;
}

// ---------------------------------------------------------------------------
// Smem operand wrapper (linear layout: this thread's matrix at p[0..d*d)).
// ---------------------------------------------------------------------------

struct SmemMat {
    const float* p;
    template <int I> __device__ __forceinline__ float at() const { return p[I]; }
};

template <int d, int col, class M, int i = 0>
__device__ __forceinline__ void load_col(const M& mat, float (&dst)[d]) {
    if constexpr (i < d) {
        dst[i] = mat.template at<i * d + col>();
        load_col<d, col, M, i + 1>(mat, dst);
    }
}

// ---------------------------------------------------------------------------
// Accumulator group (each pass/half touches only a subset; SROA drops the rest)
// ---------------------------------------------------------------------------

struct EAcc {
    float e0[1];
    float e1[9];
    float e2[25];
    float e3[49];
};

template <int L> __device__ __forceinline__ auto& getE(EAcc& a) {
    if constexpr (L == 0) return a.e0;
    else if constexpr (L == 1) return a.e1;
    else if constexpr (L == 2) return a.e2;
    else return a.e3;
}

template <int N>
__device__ __forceinline__ void zeroa(float (&e)[N]) {
#pragma unroll
    for (int i = 0; i < N; ++i) e[i] = 0.f;
}

// ---------------------------------------------------------------------------
// CG scatter: one product feeds an FFMA-imm per valid L.
// ---------------------------------------------------------------------------

template <int l1, int l2, int p, int q, int m, int n, int W, int L, int Lmax>
__device__ __forceinline__ void l_scatter(float prod, EAcc& acc) {
    if constexpr (L <= Lmax) {
        if constexpr (okL(l1, l2, L, m, n) && okL(l1, l2, L, p, q)) {
            constexpr int off = l1 + l2 - L, DL = 2 * L + 1;
            constexpr int mu = m + n - off, nu = p + q - off;
            constexpr float w = (float)((double)W * cg_elem(l1, l2, L, m - l1, n - l2) *
                                        cg_elem(l1, l2, L, p - l1, q - l2));
            getE<L>(acc)[mu * DL + nu] = __fmaf_rn(w, prod, getE<L>(acc)[mu * DL + nu]);
        }
        l_scatter<l1, l2, p, q, m, n, W, L + 1, Lmax>(prod, acc);
    }
}

template <int l1, int l2, int p, int q, int m, int BW, bool SYMIN, int Lmin, int Lmax, int n>
__device__ __forceinline__ void n_loop(float am, const float (&bcol)[2 * l2 + 1], EAcc& acc) {
    if constexpr (n < 2 * l2 + 1) {
        if constexpr (!(SYMIN && m > n) && pair_any(l1, l2, Lmin, Lmax, p, q, m, n)) {
            float prod = am * bcol[n];
            l_scatter<l1, l2, p, q, m, n, BW*((SYMIN && m < n) ? 2 : 1), Lmin, Lmax>(prod, acc);
        }
        n_loop<l1, l2, p, q, m, BW, SYMIN, Lmin, Lmax, n + 1>(am, bcol, acc);
    }
}

template <int l1, int l2, int p, int q, int BW, int Lmin, int Lmax, class MA, int m = 0>
__device__ __forceinline__ void m_loop(const MA& A, const float (&bcol)[2 * l2 + 1], EAcc& acc) {
    constexpr int d1 = 2 * l1 + 1;
    if constexpr (m < d1) {
        if constexpr (row_any(l1, l2, Lmin, Lmax, p, q, m, 0)) {
            float am = A.template at<m * d1 + p>();
            n_loop<l1, l2, p, q, m, BW, false, Lmin, Lmax, 0>(am, bcol, acc);
        }
        m_loop<l1, l2, p, q, BW, Lmin, Lmax, MA, m + 1>(A, bcol, acc);
    }
}

template <int l, int q, int Lmin, int Lmax, int m = 0>
__device__ __forceinline__ void m_loop_diag(const float (&bcol)[2 * l + 1], EAcc& acc) {
    if constexpr (m < 2 * l + 1) {
        if constexpr (row_any(l, l, Lmin, Lmax, q, q, m, m)) {
            n_loop<l, l, q, q, m, 1, true, Lmin, Lmax, m>(bcol[m], bcol, acc);
        }
        m_loop_diag<l, q, Lmin, Lmax, m + 1>(bcol, acc);
    }
}

// ----- cross term (A != B), weight BW, column-parity PAR -----

template <int l1, int l2, int BW, int Lmin, int Lmax, int PAR, class MA, int q, int p = 0>
__device__ __forceinline__ void p_multi(const MA& A, const float (&bcol)[2 * l2 + 1], EAcc& acc) {
    constexpr int d1 = 2 * l1 + 1;
    if constexpr (p < d1) {
        if constexpr (((p + q) & 1) == PAR && col_any_p(l1, l2, Lmin, Lmax, p, q)) {
            m_loop<l1, l2, p, q, BW, Lmin, Lmax, MA>(A, bcol, acc);
        }
        p_multi<l1, l2, BW, Lmin, Lmax, PAR, MA, q, p + 1>(A, bcol, acc);
    }
}

template <int l1, int l2, int BW, int Lmin, int Lmax, int PAR, class MA, class MB, int q = 0>
__device__ __forceinline__ void term_multi(const MA& A, const MB& Bm, EAcc& acc) {
    constexpr int d2 = 2 * l2 + 1;
    if constexpr (q < d2) {
        if constexpr (col_any_q_par(l1, l2, Lmin, Lmax, q, false, PAR)) {
            float bcol[d2];
            load_col<d2, q>(Bm, bcol);
            p_multi<l1, l2, BW, Lmin, Lmax, PAR, MA, q>(A, bcol, acc);
        }
        term_multi<l1, l2, BW, Lmin, Lmax, PAR, MA, MB, q + 1>(A, Bm, acc);
    }
}

// ----- symmetric self term A(x)A: p<q weight 2 full inner; p==q inner m<=n -----

template <int l, int Lmin, int Lmax, int PAR, class MA, int q, int p = 0>
__device__ __forceinline__ void p_sym_multi(const MA& A, const float (&bcol)[2 * l + 1],
                                            EAcc& acc) {
    if constexpr (p <= q) {
        if constexpr (((p + q) & 1) == PAR && col_any_p(l, l, Lmin, Lmax, p, q)) {
            if constexpr (p < q) {
                m_loop<l, l, p, q, 2, Lmin, Lmax, MA>(A, bcol, acc);
            } else {
                m_loop_diag<l, q, Lmin, Lmax>(bcol, acc);
            }
        }
        p_sym_multi<l, Lmin, Lmax, PAR, MA, q, p + 1>(A, bcol, acc);
    }
}

template <int l, int Lmin, int Lmax, int PAR, class MA, int q = 0>
__device__ __forceinline__ void term_sym_multi(const MA& A, EAcc& acc) {
    constexpr int d = 2 * l + 1;
    if constexpr (q < d) {
        if constexpr (col_any_q_par(l, l, Lmin, Lmax, q, true, PAR)) {
            float bcol[d];
            load_col<d, q>(A, bcol);
            p_sym_multi<l, Lmin, Lmax, PAR, MA, q>(A, bcol, acc);
        }
        term_sym_multi<l, Lmin, Lmax, PAR, MA, q + 1>(A, acc);
    }
}

// ----- (0,l) term, parity-filtered: e[i] += t*X[i] for owned columns only -----

template <int N, int D, int NUP, class M, int i = 0>
__device__ __forceinline__ void axpy_par(float t, const M& X, float (&e)[N]) {
    if constexpr (i < N) {
        if constexpr (((i % D) & 1) == NUP) {
            e[i] = __fmaf_rn(t, X.template at<i>(), e[i]);
        }
        axpy_par<N, D, NUP, M, i + 1>(t, X, e);
    }
}

// ----- L=0 contractions over the owned column class -----

template <int L, int NUP, class MB, int ij = 0>
__device__ __forceinline__ void invar_mat_par(const float (&A)[(2 * L + 1) * (2 * L + 1)],
                                              const MB& Bm, float& s) {
    constexpr int D = 2 * L + 1;
    if constexpr (ij < D * D) {
        if constexpr (((ij % D) & 1) == NUP) {
            constexpr int i = ij / D, j = ij % D;
            constexpr float w = (((i + j) & 1) ? -1.0f : 1.0f) / (float)D;
            s = __fmaf_rn(w, A[ij] * Bm.template at<(D - 1 - i) * D + (D - 1 - j)>(), s);
        }
        invar_mat_par<L, NUP, MB, ij + 1>(A, Bm, s);
    }
}

// partner column D-1-j has the same parity (D-1 even), so pairs stay in-class
template <int L, int NUP, int ij = 0>
__device__ __forceinline__ void invar_self_par(const float (&A)[(2 * L + 1) * (2 * L + 1)],
                                               float& s) {
    constexpr int D = 2 * L + 1, DD = D * D;
    if constexpr (ij <= (DD - 1) / 2) {
        if constexpr (((ij % D) & 1) == NUP) {
            constexpr int i = ij / D, j = ij % D;
            constexpr float base = (ij == DD - 1 - ij) ? 1.0f : 2.0f;
            constexpr float w = (((i + j) & 1) ? -base : base) / (float)D;
            s = __fmaf_rn(w, A[ij] * A[DD - 1 - ij], s);
        }
        invar_self_par<L, NUP, ij + 1>(A, s);
    }
}

// ---------------------------------------------------------------------------
// Pass bodies. PAR = column-parity class owned by this thread.
// Owned-nu parity per level: NUP(L) = (PAR + phase + L) & 1, phase = (l1+l2)&1.
// ---------------------------------------------------------------------------

template <int PAR>
__device__ __forceinline__ void passA1(const SmemMat& S1, const SmemMat& S2, const SmemMat& S3,
                                       float X0, float& out2, float& out3, float* o01) {
    EAcc a;
    zeroa(a.e0); zeroa(a.e1);
    if constexpr (PAR == 0) a.e0[0] = X0 * X0;   // (0,0) column parity 0
    term_sym_multi<1, 0, 1, PAR>(S1, a);         // (1,1) -> L=0,1
    term_sym_multi<2, 0, 1, PAR>(S2, a);         // (2,2) -> L=0,1
    term_sym_multi<3, 0, 1, PAR>(S3, a);         // (3,3) -> L=0,1
    if constexpr (PAR == 0) {
        out2 = __fmaf_rn(a.e0[0], X0, out2);
        out3 = __fmaf_rn(a.e0[0], a.e0[0], out3);
        if (o01) { o01[0] = X0; o01[1] = a.e0[0]; }
    }
    invar_self_par<1, PAR ^ 1>(a.e1, out3);      // (1,-): NUP = PAR^1
}

template <int PAR>
__device__ __forceinline__ void passA2(const SmemMat& S1, const SmemMat& S2, const SmemMat& S3,
                                       float X0, float& out2, float& out3) {
    EAcc a;
    zeroa(a.e2); zeroa(a.e3);
    term_sym_multi<1, 2, 2, PAR>(S1, a);         // (1,1) -> L=2
    term_sym_multi<2, 2, 3, PAR>(S2, a);         // (2,2) -> L=2,3
    term_sym_multi<3, 2, 3, PAR>(S3, a);         // (3,3) -> L=2,3
    term_multi<1, 3, 2, 2, 3, PAR>(S1, S3, a);   // (1,3)x2 -> L=2,3
    axpy_par<25, 5, PAR>(X0 + X0, S2, a.e2);     // (0,2)x2 -> L=2, nu=q≡PAR
    invar_mat_par<2, PAR>(a.e2, S2, out2);       // (2,+) x X2
    invar_self_par<2, PAR>(a.e2, out3);
    invar_self_par<3, PAR ^ 1>(a.e3, out3);      // (3,-): NUP = PAR^1
}

template <int PAR>
__device__ __forceinline__ void passB1(const SmemMat& S1, const SmemMat& S2, const SmemMat& S3,
                                       float X0, float& out2, float& out3) {
    EAcc a;
    zeroa(a.e1);
    axpy_par<9, 3, PAR>(X0 + X0, S1, a.e1);      // (0,1)x2 -> L=1, nu=q≡PAR
    term_multi<1, 2, 2, 1, 1, PAR>(S1, S2, a);   // (1,2)x2 -> L=1
    term_multi<2, 3, 2, 1, 1, PAR>(S2, S3, a);   // (2,3)x2 -> L=1
    invar_mat_par<1, PAR>(a.e1, S1, out2);       // (1,+) x X1
    invar_self_par<1, PAR>(a.e1, out3);
}

template <int PAR>
__device__ __forceinline__ void passB2(const SmemMat& S1, const SmemMat& S2, const SmemMat& S3,
                                       float X0, float& out2, float& out3) {
    EAcc a;
    zeroa(a.e2); zeroa(a.e3);
    term_multi<1, 2, 2, 2, 3, PAR>(S1, S2, a);   // (1,2)x2 -> L=2,3
    term_multi<2, 3, 2, 2, 3, PAR>(S2, S3, a);   // (2,3)x2 -> L=2,3
    axpy_par<49, 7, PAR>(X0 + X0, S3, a.e3);     // (0,3)x2 -> L=3, nu=q≡PAR
    invar_self_par<2, PAR ^ 1>(a.e2, out3);      // (2,-): NUP = PAR^1
    invar_mat_par<3, PAR>(a.e3, S3, out2);       // (3,+) x X3
    invar_self_par<3, PAR>(a.e3, out3);
}

// ---------------------------------------------------------------------------
// Kernel: TWO threads per batch element, split by output-column parity.
// 256-thread CTAs: warps 0-3 = parity-0 half of 128 elements, warps 4-7 =
// parity-1 half (warp-uniform branch, no divergence). Accumulators per thread
// are ~half size -> 64-reg cap, 4 CTAs/SM = 32 warps/SM.
// ---------------------------------------------------------------------------

constexpr int O0 = 0, O1 = 128, O2 = 1280, O3 = 4480, SM_FLOATS = 10752;  // 84*128

__global__ void __launch_bounds__(256, 4)
wigner_kernel(const float* __restrict__ gx0, const float* __restrict__ gx1,
              const float* __restrict__ gx2, const float* __restrict__ gx3,
              float* __restrict__ out, int n) {
    __shared__ float sm[SM_FLOATS];
    __shared__ float comb[256];
    const int tid = threadIdx.x;
    const int elem = tid & 127;
    const int half = tid >> 7;
    const int base = blockIdx.x * 128;

    if (base + 128 <= n) {  // full CTA: vectorized linear copy (256 threads)
        const float4* g0 = (const float4*)(gx0 + (size_t)base);
        const float4* g1 = (const float4*)(gx1 + (size_t)base * 9);
        const float4* g2 = (const float4*)(gx2 + (size_t)base * 25);
        const float4* g3 = (const float4*)(gx3 + (size_t)base * 49);
        float4* s = (float4*)sm;
        if (tid < 32) s[tid] = g0[tid];
#pragma unroll
        for (int i = tid; i < 288; i += 256) s[32 + i] = g1[i];
#pragma unroll
        for (int i = tid; i < 800; i += 256) s[320 + i] = g2[i];
#pragma unroll
        for (int i = tid; i < 1568; i += 256) s[1120 + i] = g3[i];
    } else {  // tail CTA: scalar with bounds
        const int c = n - base;
        for (int i = tid; i < 128; i += 256) sm[O0 + i] = (i < c) ? gx0[base + i] : 0.f;
        for (int i = tid; i < 1152; i += 256) sm[O1 + i] = (i < c * 9) ? gx1[base * 9 + i] : 0.f;
        for (int i = tid; i < 3200; i += 256) sm[O2 + i] = (i < c * 25) ? gx2[base * 25 + i] : 0.f;
        for (int i = tid; i < 6272; i += 256) sm[O3 + i] = (i < c * 49) ? gx3[base * 49 + i] : 0.f;
    }
    __syncthreads();

    const int b = base + elem;
    const bool valid = (b < n);

    const SmemMat S1{sm + O1 + elem * 9};
    const SmemMat S2{sm + O2 + elem * 25};
    const SmemMat S3{sm + O3 + elem * 49};
    const float X0 = sm[O0 + elem];

    float out2 = 0.f, out3 = 0.f;
    float* o01 = (valid && half == 0) ? (out + (size_t)b * 4) : nullptr;

    if (half == 0) passA1<0>(S1, S2, S3, X0, out2, out3, o01);
    else           passA1<1>(S1, S2, S3, X0, out2, out3, o01);
    __syncthreads();
    if (half == 0) passA2<0>(S1, S2, S3, X0, out2, out3);
    else           passA2<1>(S1, S2, S3, X0, out2, out3);
    __syncthreads();
    if (half == 0) passB1<0>(S1, S2, S3, X0, out2, out3);
    else           passB1<1>(S1, S2, S3, X0, out2, out3);
    __syncthreads();
    if (half == 0) passB2<0>(S1, S2, S3, X0, out2, out3);
    else           passB2<1>(S1, S2, S3, X0, out2, out3);

    // combine the two parity halves
    if (half == 1) {
        comb[elem] = out2;
        comb[128 + elem] = out3;
    }
    __syncthreads();
    if (half == 0 && valid) {
        out[b * 4 + 2] = out2 + comb[elem];
        out[b * 4 + 3] = out3 + comb[128 + elem];
    }
}

// ---------------------------------------------------------------------------
// Harness entry point
// ---------------------------------------------------------------------------

extern "C" void kernel_launch(void* const* d_in, const int* in_sizes, int n_in,
                              void* d_out, int out_size) {
    const float* x0 = (const float*)d_in[0];
    const float* x1 = (const float*)d_in[1];
    const float* x2 = (const float*)d_in[2];
    const float* x3 = (const float*)d_in[3];
    float* out = (float*)d_out;

    static bool attr_set = false;
    if (!attr_set) {
        cudaFuncSetAttribute(wigner_kernel,
                             cudaFuncAttributePreferredSharedMemoryCarveout, 100);
        attr_set = true;
    }

    const int n = in_sizes[0];  // B
    const int grid = (n + 127) / 128;
    wigner_kernel<<<grid, 256>>>(x0, x1, x2, x3, out, n);
}

// round 12
// speedup vs baseline: 1.3485x; 1.3485x over previous
#include <cuda_runtime.h>

// ---------------------------------------------------------------------------
// Compile-time Clebsch-Gordan coefficients (Racah formula), matching numpy ref.
// ---------------------------------------------------------------------------

__host__ __device__ constexpr double cfact(int n) {
    double r = 1.0;
    for (int i = 2; i <= n; ++i) r *= (double)i;
    return r;
}

__host__ __device__ constexpr double csqrt_(double x) {
    if (x <= 0.0) return 0.0;
    double g = x > 1.0 ? x : 1.0;
    for (int i = 0; i < 100; ++i) g = 0.5 * (g + x / g);
    return g;
}

__host__ __device__ constexpr double cg_elem(int l1, int l2, int L, int m1, int m2) {
    const int M = m1 + m2;
    if (M < -L || M > L) return 0.0;
    const double pref0 = csqrt_((2.0 * L + 1.0) * cfact(L + l1 - l2) * cfact(L - l1 + l2) *
                                cfact(l1 + l2 - L) / cfact(l1 + l2 + L + 1));
    const double pref = pref0 * csqrt_(cfact(L + M) * cfact(L - M) * cfact(l1 - m1) *
                                       cfact(l1 + m1) * cfact(l2 - m2) * cfact(l2 + m2));
    double s = 0.0;
    for (int k = 0; k <= l1 + l2 - L; ++k) {
        if (l1 - m1 - k < 0 || l2 + m2 - k < 0 || L - l2 + m1 + k < 0 || L - l1 - m2 + k < 0)
            continue;
        const double d = cfact(k) * cfact(l1 + l2 - L - k) * cfact(l1 - m1 - k) *
                         cfact(l2 + m2 - k) * cfact(L - l2 + m1 + k) * cfact(L - l1 - m2 + k);
        s += ((k & 1) ? -1.0 : 1.0) / d;
    }
    return pref * s;
}

__host__ __device__ constexpr bool cg_nz(double c) { return c > 1e-12 || c < -1e-12; }

__host__ __device__ constexpr bool okL(int l1, int l2, int L, int a, int b) {
    const int off = l1 + l2 - L;
    const int mu = a + b - off;
    return mu >= 0 && mu <= 2 * L && cg_nz(cg_elem(l1, l2, L, a - l1, b - l2));
}

__host__ __device__ constexpr bool pair_any(int l1, int l2, int Lmin, int Lmax,
                                            int p, int q, int m, int n) {
    for (int L = Lmin; L <= Lmax; ++L)
        if (okL(l1, l2, L, m, n) && okL(l1, l2, L, p, q)) return true;
    return false;
}

__host__ __device__ constexpr bool col_any_p(int l1, int l2, int Lmin, int Lmax, int p, int q) {
    for (int L = Lmin; L <= Lmax; ++L)
        if (okL(l1, l2, L, p, q)) return true;
    return false;
}

// exists a parity-owned valid p for this q?
__host__ __device__ constexpr bool col_any_q_par(int l1, int l2, int Lmin, int Lmax,
                                                 int q, bool sym, int PAR) {
    const int pmax = sym ? q : 2 * l1;
    for (int p = 0; p <= pmax; ++p)
        if (((p + q) & 1) == PAR && col_any_p(l1, l2, Lmin, Lmax, p, q)) return true;
    return false;
}

__host__ __device__ constexpr bool row_any(int l1, int l2, int Lmin, int Lmax,
                                           int p, int q, int m, int nlo) {
    for (int nn = nlo; nn <= 2 * l2; ++nn)
        if (pair_any(l1, l2, Lmin, Lmax, p, q, m, nn)) return true;
    return false;
}

// ---------------------------------------------------------------------------
// Smem operand wrapper (linear layout: this thread's matrix at p[0..d*d)).
// ---------------------------------------------------------------------------

struct SmemMat {
    const float* p;
    template <int I> __device__ __forceinline__ float at() const { return p[I]; }
};

template <int d, int col, class M, int i = 0>
__device__ __forceinline__ void load_col(const M& mat, float (&dst)[d]) {
    if constexpr (i < d) {
        dst[i] = mat.template at<i * d + col>();
        load_col<d, col, M, i + 1>(mat, dst);
    }
}

// ---------------------------------------------------------------------------
// Accumulator group (only owned-parity entries are written; rest DCE'd)
// ---------------------------------------------------------------------------

struct EAcc {
    float e0[1];
    float e1[9];
    float e2[25];
    float e3[49];
};

template <int L> __device__ __forceinline__ auto& getE(EAcc& a) {
    if constexpr (L == 0) return a.e0;
    else if constexpr (L == 1) return a.e1;
    else if constexpr (L == 2) return a.e2;
    else return a.e3;
}

template <int N>
__device__ __forceinline__ void zeroa(float (&e)[N]) {
#pragma unroll
    for (int i = 0; i < N; ++i) e[i] = 0.f;
}

// ---------------------------------------------------------------------------
// CG scatter: one product feeds an FFMA-imm per valid L in [Lmin,Lmax].
// ---------------------------------------------------------------------------

template <int l1, int l2, int p, int q, int m, int n, int W, int L, int Lmax>
__device__ __forceinline__ void l_scatter(float prod, EAcc& acc) {
    if constexpr (L <= Lmax) {
        if constexpr (okL(l1, l2, L, m, n) && okL(l1, l2, L, p, q)) {
            constexpr int off = l1 + l2 - L, DL = 2 * L + 1;
            constexpr int mu = m + n - off, nu = p + q - off;
            constexpr float w = (float)((double)W * cg_elem(l1, l2, L, m - l1, n - l2) *
                                        cg_elem(l1, l2, L, p - l1, q - l2));
            getE<L>(acc)[mu * DL + nu] = __fmaf_rn(w, prod, getE<L>(acc)[mu * DL + nu]);
        }
        l_scatter<l1, l2, p, q, m, n, W, L + 1, Lmax>(prod, acc);
    }
}

template <int l1, int l2, int p, int q, int m, int BW, bool SYMIN, int Lmin, int Lmax, int n>
__device__ __forceinline__ void n_loop(float am, const float (&bcol)[2 * l2 + 1], EAcc& acc) {
    if constexpr (n < 2 * l2 + 1) {
        if constexpr (!(SYMIN && m > n) && pair_any(l1, l2, Lmin, Lmax, p, q, m, n)) {
            float prod = am * bcol[n];
            l_scatter<l1, l2, p, q, m, n, BW*((SYMIN && m < n) ? 2 : 1), Lmin, Lmax>(prod, acc);
        }
        n_loop<l1, l2, p, q, m, BW, SYMIN, Lmin, Lmax, n + 1>(am, bcol, acc);
    }
}

template <int l1, int l2, int p, int q, int BW, int Lmin, int Lmax, class MA, int m = 0>
__device__ __forceinline__ void m_loop(const MA& A, const float (&bcol)[2 * l2 + 1], EAcc& acc) {
    constexpr int d1 = 2 * l1 + 1;
    if constexpr (m < d1) {
        if constexpr (row_any(l1, l2, Lmin, Lmax, p, q, m, 0)) {
            float am = A.template at<m * d1 + p>();
            n_loop<l1, l2, p, q, m, BW, false, Lmin, Lmax, 0>(am, bcol, acc);
        }
        m_loop<l1, l2, p, q, BW, Lmin, Lmax, MA, m + 1>(A, bcol, acc);
    }
}

template <int l, int q, int Lmin, int Lmax, int m = 0>
__device__ __forceinline__ void m_loop_diag(const float (&bcol)[2 * l + 1], EAcc& acc) {
    if constexpr (m < 2 * l + 1) {
        if constexpr (row_any(l, l, Lmin, Lmax, q, q, m, m)) {
            n_loop<l, l, q, q, m, 1, true, Lmin, Lmax, m>(bcol[m], bcol, acc);
        }
        m_loop_diag<l, q, Lmin, Lmax, m + 1>(bcol, acc);
    }
}

// ----- cross term (A != B), weight BW, column-parity PAR -----

template <int l1, int l2, int BW, int Lmin, int Lmax, int PAR, class MA, int q, int p = 0>
__device__ __forceinline__ void p_multi(const MA& A, const float (&bcol)[2 * l2 + 1], EAcc& acc) {
    constexpr int d1 = 2 * l1 + 1;
    if constexpr (p < d1) {
        if constexpr (((p + q) & 1) == PAR && col_any_p(l1, l2, Lmin, Lmax, p, q)) {
            m_loop<l1, l2, p, q, BW, Lmin, Lmax, MA>(A, bcol, acc);
        }
        p_multi<l1, l2, BW, Lmin, Lmax, PAR, MA, q, p + 1>(A, bcol, acc);
    }
}

template <int l1, int l2, int BW, int Lmin, int Lmax, int PAR, class MA, class MB, int q = 0>
__device__ __forceinline__ void term_multi(const MA& A, const MB& Bm, EAcc& acc) {
    constexpr int d2 = 2 * l2 + 1;
    if constexpr (q < d2) {
        if constexpr (col_any_q_par(l1, l2, Lmin, Lmax, q, false, PAR)) {
            float bcol[d2];
            load_col<d2, q>(Bm, bcol);
            p_multi<l1, l2, BW, Lmin, Lmax, PAR, MA, q>(A, bcol, acc);
        }
        term_multi<l1, l2, BW, Lmin, Lmax, PAR, MA, MB, q + 1>(A, Bm, acc);
    }
}

// ----- symmetric self term A(x)A: p<q weight 2 full inner; p==q inner m<=n -----

template <int l, int Lmin, int Lmax, int PAR, class MA, int q, int p = 0>
__device__ __forceinline__ void p_sym_multi(const MA& A, const float (&bcol)[2 * l + 1],
                                            EAcc& acc) {
    if constexpr (p <= q) {
        if constexpr (((p + q) & 1) == PAR && col_any_p(l, l, Lmin, Lmax, p, q)) {
            if constexpr (p < q) {
                m_loop<l, l, p, q, 2, Lmin, Lmax, MA>(A, bcol, acc);
            } else {
                m_loop_diag<l, q, Lmin, Lmax>(bcol, acc);
            }
        }
        p_sym_multi<l, Lmin, Lmax, PAR, MA, q, p + 1>(A, bcol, acc);
    }
}

template <int l, int Lmin, int Lmax, int PAR, class MA, int q = 0>
__device__ __forceinline__ void term_sym_multi(const MA& A, EAcc& acc) {
    constexpr int d = 2 * l + 1;
    if constexpr (q < d) {
        if constexpr (col_any_q_par(l, l, Lmin, Lmax, q, true, PAR)) {
            float bcol[d];
            load_col<d, q>(A, bcol);
            p_sym_multi<l, Lmin, Lmax, PAR, MA, q>(A, bcol, acc);
        }
        term_sym_multi<l, Lmin, Lmax, PAR, MA, q + 1>(A, acc);
    }
}

// ----- (0,l) term, parity-filtered: e[i] += t*X[i] for owned columns only -----

template <int N, int D, int NUP, class M, int i = 0>
__device__ __forceinline__ void axpy_par(float t, const M& X, float (&e)[N]) {
    if constexpr (i < N) {
        if constexpr (((i % D) & 1) == NUP) {
            e[i] = __fmaf_rn(t, X.template at<i>(), e[i]);
        }
        axpy_par<N, D, NUP, M, i + 1>(t, X, e);
    }
}

// ----- L=0 contractions over the owned column class -----

template <int L, int NUP, class MB, int ij = 0>
__device__ __forceinline__ void invar_mat_par(const float (&A)[(2 * L + 1) * (2 * L + 1)],
                                              const MB& Bm, float& s) {
    constexpr int D = 2 * L + 1;
    if constexpr (ij < D * D) {
        if constexpr (((ij % D) & 1) == NUP) {
            constexpr int i = ij / D, j = ij % D;
            constexpr float w = (((i + j) & 1) ? -1.0f : 1.0f) / (float)D;
            s = __fmaf_rn(w, A[ij] * Bm.template at<(D - 1 - i) * D + (D - 1 - j)>(), s);
        }
        invar_mat_par<L, NUP, MB, ij + 1>(A, Bm, s);
    }
}

// partner column D-1-j has the same parity (D-1 even), so pairs stay in-class
template <int L, int NUP, int ij = 0>
__device__ __forceinline__ void invar_self_par(const float (&A)[(2 * L + 1) * (2 * L + 1)],
                                               float& s) {
    constexpr int D = 2 * L + 1, DD = D * D;
    if constexpr (ij <= (DD - 1) / 2) {
        if constexpr (((ij % D) & 1) == NUP) {
            constexpr int i = ij / D, j = ij % D;
            constexpr float base = (ij == DD - 1 - ij) ? 1.0f : 2.0f;
            constexpr float w = (((i + j) & 1) ? -base : base) / (float)D;
            s = __fmaf_rn(w, A[ij] * A[DD - 1 - ij], s);
        }
        invar_self_par<L, NUP, ij + 1>(A, s);
    }
}

// ---------------------------------------------------------------------------
// Pass bodies. PAR = column-parity class owned by this thread.
// Phase A (l1+l2 even): blocks (0,+),(1,-),(2,+),(3,-); NUP(L) = (PAR+L)&1.
// Phase B (l1+l2 odd):  blocks (1,+),(2,-),(3,+);       NUP(L) = (PAR+1+L)&1.
// Each phase does ALL its L's in one pass (products shared across L).
// ---------------------------------------------------------------------------

template <int PAR>
__device__ __forceinline__ void passA(const SmemMat& S1, const SmemMat& S2, const SmemMat& S3,
                                      float X0, float& out2, float& out3, float* o01) {
    EAcc a;
    zeroa(a.e0); zeroa(a.e1); zeroa(a.e2); zeroa(a.e3);
    if constexpr (PAR == 0) a.e0[0] = X0 * X0;   // (0,0) column parity 0
    term_sym_multi<1, 0, 2, PAR>(S1, a);         // (1,1) -> L=0,1,2
    term_sym_multi<2, 0, 3, PAR>(S2, a);         // (2,2) -> L=0..3
    term_sym_multi<3, 0, 3, PAR>(S3, a);         // (3,3) -> L=0..3
    term_multi<1, 3, 2, 2, 3, PAR>(S1, S3, a);   // (1,3)x2 -> L=2,3
    axpy_par<25, 5, PAR>(X0 + X0, S2, a.e2);     // (0,2)x2 -> L=2, nu=q≡PAR
    if constexpr (PAR == 0) {
        out2 = __fmaf_rn(a.e0[0], X0, out2);
        out3 = __fmaf_rn(a.e0[0], a.e0[0], out3);
        if (o01) { o01[0] = X0; o01[1] = a.e0[0]; }
    }
    invar_self_par<1, PAR ^ 1>(a.e1, out3);      // (1,-)
    invar_mat_par<2, PAR>(a.e2, S2, out2);       // (2,+) x X2
    invar_self_par<2, PAR>(a.e2, out3);
    invar_self_par<3, PAR ^ 1>(a.e3, out3);      // (3,-)
}

template <int PAR>
__device__ __forceinline__ void passB(const SmemMat& S1, const SmemMat& S2, const SmemMat& S3,
                                      float X0, float& out2, float& out3) {
    EAcc a;
    zeroa(a.e1); zeroa(a.e2); zeroa(a.e3);
    axpy_par<9, 3, PAR>(X0 + X0, S1, a.e1);      // (0,1)x2 -> L=1, nu=q≡PAR
    term_multi<1, 2, 2, 1, 3, PAR>(S1, S2, a);   // (1,2)x2 -> L=1..3
    term_multi<2, 3, 2, 1, 3, PAR>(S2, S3, a);   // (2,3)x2 -> L=1..3
    axpy_par<49, 7, PAR>(X0 + X0, S3, a.e3);     // (0,3)x2 -> L=3, nu=q≡PAR
    invar_mat_par<1, PAR>(a.e1, S1, out2);       // (1,+) x X1
    invar_self_par<1, PAR>(a.e1, out3);
    invar_self_par<2, PAR ^ 1>(a.e2, out3);      // (2,-)
    invar_mat_par<3, PAR>(a.e3, S3, out2);       // (3,+) x X3
    invar_self_par<3, PAR>(a.e3, out3);
}

// ---------------------------------------------------------------------------
// Kernel: TWO threads per batch element, split by output-column parity.
// 256-thread CTAs: warps 0-3 = parity-0 half, warps 4-7 = parity-1 half
// (warp-uniform branch). 84-reg cap (3 CTAs/SM, 24 warps/SM) — spill-free
// with ~19 regs of headroom (the 64-reg cap in round 11 spilled hot accs).
// ---------------------------------------------------------------------------

constexpr int O0 = 0, O1 = 128, O2 = 1280, O3 = 4480, SM_FLOATS = 10752;  // 84*128

__global__ void __launch_bounds__(256, 3)
wigner_kernel(const float* __restrict__ gx0, const float* __restrict__ gx1,
              const float* __restrict__ gx2, const float* __restrict__ gx3,
              float* __restrict__ out, int n) {
    __shared__ float sm[SM_FLOATS];
    __shared__ float comb[256];
    const int tid = threadIdx.x;
    const int elem = tid & 127;
    const int half = tid >> 7;
    const int base = blockIdx.x * 128;

    if (base + 128 <= n) {  // full CTA: vectorized linear copy (256 threads)
        const float4* g0 = (const float4*)(gx0 + (size_t)base);
        const float4* g1 = (const float4*)(gx1 + (size_t)base * 9);
        const float4* g2 = (const float4*)(gx2 + (size_t)base * 25);
        const float4* g3 = (const float4*)(gx3 + (size_t)base * 49);
        float4* s = (float4*)sm;
        if (tid < 32) s[tid] = g0[tid];
#pragma unroll
        for (int i = tid; i < 288; i += 256) s[32 + i] = g1[i];
#pragma unroll
        for (int i = tid; i < 800; i += 256) s[320 + i] = g2[i];
#pragma unroll
        for (int i = tid; i < 1568; i += 256) s[1120 + i] = g3[i];
    } else {  // tail CTA: scalar with bounds
        const int c = n - base;
        for (int i = tid; i < 128; i += 256) sm[O0 + i] = (i < c) ? gx0[base + i] : 0.f;
        for (int i = tid; i < 1152; i += 256) sm[O1 + i] = (i < c * 9) ? gx1[base * 9 + i] : 0.f;
        for (int i = tid; i < 3200; i += 256) sm[O2 + i] = (i < c * 25) ? gx2[base * 25 + i] : 0.f;
        for (int i = tid; i < 6272; i += 256) sm[O3 + i] = (i < c * 49) ? gx3[base * 49 + i] : 0.f;
    }
    __syncthreads();

    const int b = base + elem;
    const bool valid = (b < n);

    const SmemMat S1{sm + O1 + elem * 9};
    const SmemMat S2{sm + O2 + elem * 25};
    const SmemMat S3{sm + O3 + elem * 49};
    const float X0 = sm[O0 + elem];

    float out2 = 0.f, out3 = 0.f;
    float* o01 = (valid && half == 0) ? (out + (size_t)b * 4) : nullptr;

    if (half == 0) passA<0>(S1, S2, S3, X0, out2, out3, o01);
    else           passA<1>(S1, S2, S3, X0, out2, out3, o01);
    __syncthreads();
    if (half == 0) passB<0>(S1, S2, S3, X0, out2, out3);
    else           passB<1>(S1, S2, S3, X0, out2, out3);

    // combine the two parity halves
    if (half == 1) {
        comb[elem] = out2;
        comb[128 + elem] = out3;
    }
    __syncthreads();
    if (half == 0 && valid) {
        out[b * 4 + 2] = out2 + comb[elem];
        out[b * 4 + 3] = out3 + comb[128 + elem];
    }
}

// ---------------------------------------------------------------------------
// Harness entry point
// ---------------------------------------------------------------------------

extern "C" void kernel_launch(void* const* d_in, const int* in_sizes, int n_in,
                              void* d_out, int out_size) {
    const float* x0 = (const float*)d_in[0];
    const float* x1 = (const float*)d_in[1];
    const float* x2 = (const float*)d_in[2];
    const float* x3 = (const float*)d_in[3];
    float* out = (float*)d_out;

    static bool attr_set = false;
    if (!attr_set) {
        cudaFuncSetAttribute(wigner_kernel,
                             cudaFuncAttributePreferredSharedMemoryCarveout, 100);
        attr_set = true;
    }

    const int n = in_sizes[0];  // B
    const int grid = (n + 127) / 128;
    wigner_kernel<<<grid, 256>>>(x0, x1, x2, x3, out, n);
}